// round 8
// baseline (speedup 1.0000x reference)
#include <cuda_runtime.h>
#include <stdint.h>

#define DINL __device__ __forceinline__
constexpr int MTOK = 16384;   // 8 * 2048 tokens

// ---------------- scratch (device globals; no dynamic alloc) ----------------
__device__ __align__(16) float g_Z [MTOK*1024];
__device__ __align__(16) float g_P [MTOK*128];
__device__ __align__(16) float g_R [MTOK*64];
__device__ __align__(16) float g_P2[MTOK*128];
__device__ __align__(16) float g_P3[MTOK*128];
__device__ __align__(16) float g_G [MTOK*1024];
__device__ __align__(16) float g_U [MTOK*1024];
__device__ __align__(16) float g_FG[(size_t)MTOK*3072];
__device__ __align__(16) float g_FF[(size_t)MTOK*3072];
// packed tf32 weights, K-major [K][N]
__device__ __align__(16) float g_WBfg [8*288*128];
__device__ __align__(16) float g_WBgu [8*288*128];
__device__ __align__(16) float g_WBffg[8*160*384];
__device__ __align__(16) float g_WBfff[8*160*384];
__device__ __align__(16) float g_WBffp[8*384*128];
__device__ __align__(16) float g_PB  [1024*128];
__device__ __align__(16) float g_PB2 [1024*128];
__device__ __align__(16) float g_PB3 [3072*128];

DINL float tf32r(float x){ unsigned u; asm("cvt.rna.tf32.f32 %0,%1;":"=r"(u):"f"(x)); return __uint_as_float(u); }

DINL void mma8(float* d, const unsigned* a, const unsigned* b){
    asm volatile("mma.sync.aligned.m16n8k8.row.col.f32.tf32.tf32.f32 "
        "{%0,%1,%2,%3},{%4,%5,%6,%7},{%8,%9},{%0,%1,%2,%3};"
        :"+f"(d[0]),"+f"(d[1]),"+f"(d[2]),"+f"(d[3])
        :"r"(a[0]),"r"(a[1]),"r"(a[2]),"r"(a[3]),"r"(b[0]),"r"(b[1]));
}

// ---------------------------------------------------------------------------
// Generic GEMM: C[128 x 128-tile] = A[128 x KTOT] * B[KTOT x 128] (+H) per
// (mtile, diag-block b, n-tile).  A region1: A1[(m-shift)*lda1 + aoff + k],
// k<K1 (zero row at sequence start when shifted).  A region2 (K-extension):
// A2[m*lda2 + a2off + (k-K1)].  B: Bw + b*bBlkStride, row stride ldbN.
// ---------------------------------------------------------------------------
__global__ void __launch_bounds__(512,1) k_gemm(
    const float* __restrict__ A1, int lda1, int blkStrideA, int shiftMode,
    const float* __restrict__ A2, int lda2, int a2off,
    const float* __restrict__ Bw, int ldbN, int bBlkStride,
    float* __restrict__ C, int ldc, int cBlkStride,
    const float* __restrict__ Hadd, int K1, int KTOT, int roundC)
{
    __shared__ float As[128*20];
    __shared__ float Bs[16*136];
    const int b = blockIdx.y, nt = blockIdx.z;
    bool shift=false; int aoff;
    if (shiftMode){ shift = (b>=4); aoff=(b&3)*blkStrideA; } else aoff=b*blkStrideA;
    const float* Bp = Bw + (size_t)b*bBlkStride + nt*128;
    const int tid=threadIdx.x, warp=tid>>5, lane=tid&31;
    const int wm=warp>>2, wn=warp&3, gid=lane>>2, tig=lane&3;
    const int akk=tid&15, arow=tid>>4;
    const int m0=blockIdx.x*128;
    float acc[2][4][4];
#pragma unroll
    for(int i=0;i<2;i++)
#pragma unroll
        for(int j=0;j<4;j++)
#pragma unroll
            for(int q=0;q<4;q++) acc[i][j][q]=0.f;
    float pa[4], pb[4];
    const int nsteps = KTOT/16;

    auto loadG=[&](int k0){
        if(k0 < K1){
#pragma unroll
            for(int i=0;i<4;i++){
                int m=m0+arow+32*i; float v=0.f;
                if(!shift || (m&2047)) v = A1[(size_t)(m-(shift?1:0))*lda1 + aoff + k0 + akk];
                pa[i]=v;
            }
        } else {
#pragma unroll
            for(int i=0;i<4;i++){
                int m=m0+arow+32*i;
                pa[i]=A2[(size_t)m*lda2 + a2off + (k0-K1) + akk];
            }
        }
#pragma unroll
        for(int i=0;i<4;i++){
            int idx=tid+i*512, r=idx>>7, c=idx&127;
            pb[i]=Bp[(size_t)(k0+r)*ldbN + c];
        }
    };
    auto stS=[&](){
#pragma unroll
        for(int i=0;i<4;i++) As[(arow+32*i)*20+akk]=pa[i];
#pragma unroll
        for(int i=0;i<4;i++){ int idx=tid+i*512; Bs[(idx>>7)*136+(idx&127)]=pb[i]; }
    };

    loadG(0); stS(); __syncthreads();
    for(int s=0;s<nsteps;s++){
        if(s+1<nsteps) loadG((s+1)*16);
#pragma unroll
        for(int k8=0;k8<2;k8++){
            unsigned af[2][4];
#pragma unroll
            for(int mf=0;mf<2;mf++){
                int r0=wm*32+mf*16+gid, c=k8*8+tig;
                af[mf][0]=__float_as_uint(As[r0*20+c]);
                af[mf][1]=__float_as_uint(As[(r0+8)*20+c]);
                af[mf][2]=__float_as_uint(As[r0*20+c+4]);
                af[mf][3]=__float_as_uint(As[(r0+8)*20+c+4]);
            }
#pragma unroll
            for(int nf=0;nf<4;nf++){
                unsigned bf[2];
                int col=wn*32+nf*8+gid;
                bf[0]=__float_as_uint(Bs[(k8*8+tig)*136+col]);
                bf[1]=__float_as_uint(Bs[(k8*8+tig+4)*136+col]);
                mma8(acc[0][nf],af[0],bf);
                mma8(acc[1][nf],af[1],bf);
            }
        }
        __syncthreads();
        if(s+1<nsteps){ stS(); __syncthreads(); }
    }
    const int coff = b*cBlkStride + nt*128;
#pragma unroll
    for(int mf=0;mf<2;mf++){
        int m=m0+wm*32+mf*16+gid;
#pragma unroll
        for(int nf=0;nf<4;nf++){
            int col=coff+wn*32+nf*8+2*tig;
            float v0=acc[mf][nf][0], v1=acc[mf][nf][1], v2=acc[mf][nf][2], v3=acc[mf][nf][3];
            if(Hadd){
                v0+=Hadd[(size_t)m*ldc+col];     v1+=Hadd[(size_t)m*ldc+col+1];
                v2+=Hadd[(size_t)(m+8)*ldc+col]; v3+=Hadd[(size_t)(m+8)*ldc+col+1];
            }
            if(roundC){ v0=tf32r(v0); v1=tf32r(v1); v2=tf32r(v2); v3=tf32r(v3); }
            C[(size_t)m*ldc+col]=v0;     C[(size_t)m*ldc+col+1]=v1;
            C[(size_t)(m+8)*ldc+col]=v2; C[(size_t)(m+8)*ldc+col+1]=v3;
        }
    }
}

// ---------------- weight repack (tf32-rounded, K-major packed) --------------
__global__ void k_prep(
    const float* __restrict__ fgW,const float* __restrict__ fgA,const float* __restrict__ fgB,
    const float* __restrict__ guW,const float* __restrict__ guA,const float* __restrict__ guB,
    const float* __restrict__ ffgW,const float* __restrict__ ffgA,const float* __restrict__ ffgB,
    const float* __restrict__ fffW,const float* __restrict__ fffA,const float* __restrict__ fffB,
    const float* __restrict__ ffpW,const float* __restrict__ ffpA,const float* __restrict__ ffpB)
{
    const int S1=8*288*128, S2=S1, S3=8*160*384, S4=S3, S5=8*384*128;
    const int S6=1024*128, S7=1024*128, S8=3072*128;
    const int TOT=S1+S2+S3+S4+S5+S6+S7+S8;
    for(int idx=blockIdx.x*blockDim.x+threadIdx.x; idx<TOT; idx+=gridDim.x*blockDim.x){
        int i=idx; float v=0.f; float* dst;
        if(i<S1){ int b=i/36864,r=i%36864,k=r>>7,n=r&127,row=b*128+n;
            v = (k<256)? fgW[row*256+k] : fgA[row*32+(k-256)]; dst=&g_WBfg[i];
        } else if((i-=S1)<S2){ int b=i/36864,r=i%36864,k=r>>7,n=r&127,row=b*128+n;
            v = (k<256)? guW[row*256+k] : guA[row*32+(k-256)]; dst=&g_WBgu[i];
        } else if((i-=S2)<S3){ int b=i/61440,r=i%61440,k=r/384,n=r%384;
            if(n<352){ int row=b*352+n; v=(k<128)? ffgW[row*128+k] : ffgA[row*32+(k-128)]; }
            dst=&g_WBffg[i];
        } else if((i-=S3)<S4){ int b=i/61440,r=i%61440,k=r/384,n=r%384;
            if(n<352){ int row=b*352+n; v=(k<128)? fffW[row*128+k] : fffA[row*32+(k-128)]; }
            dst=&g_WBfff[i];
        } else if((i-=S4)<S5){ int b=i/49152,r=i%49152,k=r>>7,n=r&127,row=b*128+n;
            v = (k<352)? ffpW[row*352+k] : ffpA[row*32+(k-352)]; dst=&g_WBffp[i];
        } else if((i-=S5)<S6){ int k=i>>7,c=i&127;
            v = (c<32)? fgB[c*2048+k] : (c<64)? fgB[(c-32)*2048+1024+k]
              : (c<96)? guB[(c-64)*2048+k] : guB[(c-96)*2048+1024+k];
            dst=&g_PB[i];
        } else if((i-=S6)<S7){ int k=i>>7,c=i&127;
            v = (c<32)? ffgB[c*1024+k] : (c<64)? fffB[(c-32)*1024+k] : 0.f;
            dst=&g_PB2[i];
        } else { i-=S7; int k=i>>7,c=i&127,kk=k%384;
            v = (c<32 && kk<352)? ffpB[c*2816 + (k/384)*352 + kk] : 0.f;
            dst=&g_PB3[i];
        }
        *dst = tf32r(v);
    }
}

// ---------------- rmsnorm: one warp per token, write tf32-rounded Z ---------
__global__ void __launch_bounds__(256) k_rms(const float* __restrict__ H){
    int warp=threadIdx.x>>5, lane=threadIdx.x&31;
    int m=blockIdx.x*8+warp;
    const float4* hp=reinterpret_cast<const float4*>(H)+(size_t)m*256;
    float4 v[8]; float ss=0.f;
#pragma unroll
    for(int j=0;j<8;j++){ v[j]=hp[j*32+lane];
        ss+=v[j].x*v[j].x+v[j].y*v[j].y+v[j].z*v[j].z+v[j].w*v[j].w; }
#pragma unroll
    for(int o=16;o;o>>=1) ss+=__shfl_xor_sync(0xffffffffu,ss,o);
    float sc=rsqrtf(ss*(1.f/1024.f)+1.1920929e-07f);
    float4* zp=reinterpret_cast<float4*>(g_Z)+(size_t)m*256;
#pragma unroll
    for(int j=0;j<8;j++){ float4 o4;
        o4.x=tf32r(v[j].x*sc); o4.y=tf32r(v[j].y*sc);
        o4.z=tf32r(v[j].z*sc); o4.w=tf32r(v[j].w*sc);
        zp[j*32+lane]=o4; }
}

// R[m,c<32]=r_fg, R[m,32..63]=r_gu  (shifted part from previous token's P)
__global__ void k_r1(){
    int idx=blockIdx.x*blockDim.x+threadIdx.x;
    if(idx>=MTOK*64) return;
    int m=idx>>6, c=idx&63;
    int base=(c<32)? c : c+32;
    float v=g_P[(size_t)m*128+base];
    if(m&2047) v+=g_P[(size_t)(m-1)*128+base+32];
    g_R[idx]=tf32r(v);
}

// h += sigmoid(G)*U   (float4 over 16384x1024)
__global__ void k_gate(float* __restrict__ H){
    size_t i=(size_t)blockIdx.x*blockDim.x+threadIdx.x;
    float4 g=((const float4*)g_G)[i], u=((const float4*)g_U)[i], h=((float4*)H)[i];
    h.x += u.x/(1.f+__expf(-g.x));
    h.y += u.y/(1.f+__expf(-g.y));
    h.z += u.z/(1.f+__expf(-g.z));
    h.w += u.w/(1.f+__expf(-g.w));
    ((float4*)H)[i]=h;
}

// FF = tf32r(silu(FG)*FFf) in place on FG (padded cols stay 0)
__global__ void k_ff(){
    size_t i=(size_t)blockIdx.x*blockDim.x+threadIdx.x;   // float4 over MTOK*768
    int col4=(int)(i%768); int jj=col4%96;
    if(jj>=88) return;
    float4 g=((const float4*)g_FG)[i], f=((const float4*)g_FF)[i], o;
    o.x=tf32r(f.x*g.x/(1.f+__expf(-g.x)));
    o.y=tf32r(f.y*g.y/(1.f+__expf(-g.y)));
    o.z=tf32r(f.z*g.z/(1.f+__expf(-g.z)));
    o.w=tf32r(f.w*g.w/(1.f+__expf(-g.w)));
    ((float4*)g_FG)[i]=o;
}

// ---------------------------------------------------------------------------
extern "C" void kernel_launch(void* const* d_in, const int* in_sizes, int n_in,
                              void* d_out, int out_size)
{
    (void)in_sizes; (void)n_in; (void)out_size;
    const float* x   =(const float*)d_in[0];
    const float* fgW =(const float*)d_in[1],  *fgA =(const float*)d_in[2],  *fgB =(const float*)d_in[3];
    const float* guW =(const float*)d_in[4],  *guA =(const float*)d_in[5],  *guB =(const float*)d_in[6];
    const float* ffgW=(const float*)d_in[7],  *ffgA=(const float*)d_in[8],  *ffgB=(const float*)d_in[9];
    const float* fffW=(const float*)d_in[10], *fffA=(const float*)d_in[11], *fffB=(const float*)d_in[12];
    const float* ffpW=(const float*)d_in[13], *ffpA=(const float*)d_in[14], *ffpB=(const float*)d_in[15];
    float* H=(float*)d_out;

    float *Z,*P,*R,*P2,*P3,*G,*U,*FG,*FF,*WBfg,*WBgu,*WBffg,*WBfff,*WBffp,*PB,*PB2,*PB3;
    cudaGetSymbolAddress((void**)&Z,  g_Z );  cudaGetSymbolAddress((void**)&P,  g_P );
    cudaGetSymbolAddress((void**)&R,  g_R );  cudaGetSymbolAddress((void**)&P2, g_P2);
    cudaGetSymbolAddress((void**)&P3, g_P3);  cudaGetSymbolAddress((void**)&G,  g_G );
    cudaGetSymbolAddress((void**)&U,  g_U );  cudaGetSymbolAddress((void**)&FG, g_FG);
    cudaGetSymbolAddress((void**)&FF, g_FF);  cudaGetSymbolAddress((void**)&WBfg, g_WBfg);
    cudaGetSymbolAddress((void**)&WBgu, g_WBgu); cudaGetSymbolAddress((void**)&WBffg,g_WBffg);
    cudaGetSymbolAddress((void**)&WBfff,g_WBfff);cudaGetSymbolAddress((void**)&WBffp,g_WBffp);
    cudaGetSymbolAddress((void**)&PB, g_PB);  cudaGetSymbolAddress((void**)&PB2,g_PB2);
    cudaGetSymbolAddress((void**)&PB3,g_PB3);

    cudaMemcpyAsync(H, x, (size_t)MTOK*1024*sizeof(float), cudaMemcpyDeviceToDevice);
    k_prep<<<4096,256>>>(fgW,fgA,fgB,guW,guA,guB,ffgW,ffgA,ffgB,fffW,fffA,fffB,ffpW,ffpA,ffpB);

    dim3 g1(128,1,1), gBlk(128,8,1), gFf(128,8,3);
    for(int it=0; it<4; it++){
        k_rms<<<2048,256>>>(H);
        // P = Z @ [B1fg|B2fg|B1gu|B2gu]^T   (K=1024, N=128)
        k_gemm<<<g1,512>>>(Z,1024,0,0, (const float*)0,0,0, PB,128,0, P,128,0,
                           (const float*)0, 1024,1024,1);
        k_r1<<<MTOK*64/256,256>>>();
        // gate / update block GEMMs with K-extension (K=256+32)
        k_gemm<<<gBlk,512>>>(Z,1024,256,1, R,64,0,  WBfg,128,288*128, G,1024,128,
                             (const float*)0, 256,288,1);
        k_gemm<<<gBlk,512>>>(Z,1024,256,1, R,64,32, WBgu,128,288*128, U,1024,128,
                             (const float*)0, 256,288,1);
        k_gate<<<MTOK*256/256,256>>>(H);
    }
    k_rms<<<2048,256>>>(H);
    // P2 = Z @ [Bffg|Bfff]^T (padded to N=128)
    k_gemm<<<g1,512>>>(Z,1024,0,0, (const float*)0,0,0, PB2,128,0, P2,128,0,
                       (const float*)0, 1024,1024,1);
    // ffg / fff (K=128+32, N padded 384/block, C stride 3072)
    k_gemm<<<gFf,512>>>(Z,1024,128,0, P2,128,0,  WBffg,384,160*384, FG,3072,384,
                        (const float*)0, 128,160,1);
    k_gemm<<<gFf,512>>>(Z,1024,128,0, P2,128,32, WBfff,384,160*384, FF,3072,384,
                        (const float*)0, 128,160,1);
    k_ff<<<MTOK*768/256,256>>>();
    // P3 = FF @ Bffp^T (padded K=3072, N=128)
    k_gemm<<<g1,512>>>(FG,3072,0,0, (const float*)0,0,0, PB3,128,0, P3,128,0,
                       (const float*)0, 3072,3072,1);
    // out = h + ffp(FF)   (K=352+32)
    k_gemm<<<gBlk,512>>>(FG,3072,384,0, P3,128,0, WBffp,128,384*128, H,1024,128,
                         H, 352,384,0);
}

// round 10
// speedup vs baseline: 1.0229x; 1.0229x over previous
#include <cuda_runtime.h>
#include <stdint.h>

#define DINL __device__ __forceinline__
constexpr int MTOK = 16384;   // 8 * 2048 tokens

// ---------------- scratch (device globals; no dynamic alloc) ----------------
__device__ __align__(16) float g_Z [MTOK*1024];
__device__ __align__(16) float g_P [MTOK*128];
__device__ __align__(16) float g_R [MTOK*64];
__device__ __align__(16) float g_P2[MTOK*128];
__device__ __align__(16) float g_P3[MTOK*128];
__device__ __align__(16) float g_G [MTOK*1024];
__device__ __align__(16) float g_FG[(size_t)MTOK*3072];
// packed tf32 weights, K-major [K][N]
__device__ __align__(16) float g_WBfg [8*288*128];
__device__ __align__(16) float g_WBgu [8*288*128];
__device__ __align__(16) float g_WBffg[8*160*384];
__device__ __align__(16) float g_WBfff[8*160*384];
__device__ __align__(16) float g_WBffp[8*384*128];
__device__ __align__(16) float g_PB  [1024*128];
__device__ __align__(16) float g_PB2 [1024*128];
__device__ __align__(16) float g_PB3 [3072*128];

DINL float tf32r(float x){ unsigned u; asm("cvt.rna.tf32.f32 %0,%1;":"=r"(u):"f"(x)); return __uint_as_float(u); }

DINL void mma8(float* d, const unsigned* a, const unsigned* b){
    asm volatile("mma.sync.aligned.m16n8k8.row.col.f32.tf32.tf32.f32 "
        "{%0,%1,%2,%3},{%4,%5,%6,%7},{%8,%9},{%0,%1,%2,%3};"
        :"+f"(d[0]),"+f"(d[1]),"+f"(d[2]),"+f"(d[3])
        :"r"(a[0]),"r"(a[1]),"r"(a[2]),"r"(a[3]),"r"(b[0]),"r"(b[1]));
}
DINL void cpa16(uint32_t s, const void* g, int sz){
    asm volatile("cp.async.cg.shared.global [%0], [%1], 16, %2;"::"r"(s),"l"(g),"r"(sz));
}
DINL void cpcommit(){ asm volatile("cp.async.commit_group;"); }
template<int N> DINL void cpwait(){ asm volatile("cp.async.wait_group %0;"::"n"(N)); }

// ---------------------------------------------------------------------------
// GEMM: C[128 x 128] per (mtile, diag-block b, n-tile). K-chunk 32,
// cp.async double-buffered.  A region1 (k<K1): A1[(m-shift)*lda1+aoff+k]
// (zero row at sequence start when shifted). A region2: A2[m*lda2+a2off+k-K1].
// mode 0: C = (acc + Hadd?) (tf32r if roundC)
// mode 1: C += sigmoid(Gbuf)*acc            (gate-update fusion, C==H)
// mode 2: C  = tf32r(silu(Gbuf)*acc)        (ff fusion, Gbuf==C==FG)
// ---------------------------------------------------------------------------
constexpr int ASZ = 128*36;    // per-stage A floats
constexpr int BSZ = 32*136;    // per-stage B floats
constexpr int SMEMB = (2*ASZ + 2*BSZ) * 4;   // 71680 bytes

__global__ void __launch_bounds__(512,1) k_gemm(
    const float* __restrict__ A1, int lda1, int blkStrideA, int shiftMode,
    const float* __restrict__ A2, int lda2, int a2off,
    const float* __restrict__ Bw, int ldbN, int bBlkStride,
    float* __restrict__ C, int ldc, int cBlkStride,
    const float* __restrict__ Hadd, const float* __restrict__ Gbuf,
    int K1, int KTOT, int roundC, int mode)
{
    extern __shared__ float sm[];
    float* As[2] = { sm, sm + ASZ };
    float* Bs[2] = { sm + 2*ASZ, sm + 2*ASZ + BSZ };

    const int b = blockIdx.y, nt = blockIdx.z;
    bool shift=false; int aoff;
    if (shiftMode){ shift=(b>=4); aoff=(b&3)*blkStrideA; } else aoff=b*blkStrideA;
    const float* Bp = Bw + (size_t)b*bBlkStride + nt*128;
    const int tid=threadIdx.x, warp=tid>>5, lane=tid&31;
    const int wm=warp>>2, wn=warp&3, gid=lane>>2, tig=lane&3;
    const int m0=blockIdx.x*128;
    const int nsteps = KTOT/32;

    float acc[2][4][4];
#pragma unroll
    for(int i=0;i<2;i++)
#pragma unroll
        for(int j=0;j<4;j++)
#pragma unroll
            for(int q=0;q<4;q++) acc[i][j][q]=0.f;

    auto fill=[&](int st, int k0){
        bool r1 = (k0 < K1);
#pragma unroll
        for(int j=0;j<2;j++){
            int id = tid + j*512;          // 0..1023  -> A 128x32
            int row = id>>3, kc=(id&7)*4;
            uint32_t sa = (uint32_t)__cvta_generic_to_shared(&As[st][row*36+kc]);
            int m=m0+row; int sz=16; const float* gp;
            if(r1){
                int mm=m;
                if(shift){ if((m&2047)==0) sz=0; else mm=m-1; }
                gp = &A1[(size_t)mm*lda1 + aoff + k0 + kc];
            } else {
                gp = &A2[(size_t)m*lda2 + a2off + (k0-K1) + kc];
            }
            cpa16(sa, gp, sz);
        }
#pragma unroll
        for(int j=0;j<2;j++){
            int id = tid + j*512;          // 0..1023  -> B 32x128
            int r=id>>5, c=(id&31)*4;
            uint32_t sb = (uint32_t)__cvta_generic_to_shared(&Bs[st][r*136+c]);
            cpa16(sb, &Bp[(size_t)(k0+r)*ldbN + c], 16);
        }
    };

    fill(0, 0); cpcommit();
    for(int s=0;s<nsteps;s++){
        const int st = s&1;
        if(s+1<nsteps){ fill(st^1, (s+1)*32); cpcommit(); cpwait<1>(); }
        else cpwait<0>();
        __syncthreads();
        const float* AsS=As[st]; const float* BsS=Bs[st];
#pragma unroll
        for(int k8=0;k8<4;k8++){
            unsigned af[2][4];
#pragma unroll
            for(int mf=0;mf<2;mf++){
                int r0=wm*32+mf*16+gid, c=k8*8+tig;
                af[mf][0]=__float_as_uint(AsS[r0*36+c]);
                af[mf][1]=__float_as_uint(AsS[(r0+8)*36+c]);
                af[mf][2]=__float_as_uint(AsS[r0*36+c+4]);
                af[mf][3]=__float_as_uint(AsS[(r0+8)*36+c+4]);
            }
#pragma unroll
            for(int nf=0;nf<4;nf++){
                unsigned bf[2];
                int col=wn*32+nf*8+gid;
                bf[0]=__float_as_uint(BsS[(k8*8+tig)*136+col]);
                bf[1]=__float_as_uint(BsS[(k8*8+tig+4)*136+col]);
                mma8(acc[0][nf],af[0],bf);
                mma8(acc[1][nf],af[1],bf);
            }
        }
        __syncthreads();
    }

    const int coff = b*cBlkStride + nt*128;
#pragma unroll
    for(int mf=0;mf<2;mf++){
        int m=m0+wm*32+mf*16+gid;
#pragma unroll
        for(int nf=0;nf<4;nf++){
            int col=coff+wn*32+nf*8+2*tig;
            size_t i0=(size_t)m*ldc+col, i2=(size_t)(m+8)*ldc+col;
            float a0=acc[mf][nf][0], a1=acc[mf][nf][1], a2=acc[mf][nf][2], a3=acc[mf][nf][3];
            if(mode==0){
                if(Hadd){ a0+=Hadd[i0]; a1+=Hadd[i0+1]; a2+=Hadd[i2]; a3+=Hadd[i2+1]; }
                if(roundC){ a0=tf32r(a0); a1=tf32r(a1); a2=tf32r(a2); a3=tf32r(a3); }
                C[i0]=a0; C[i0+1]=a1; C[i2]=a2; C[i2+1]=a3;
            } else if(mode==1){
                float g0=Gbuf[i0], g1=Gbuf[i0+1], g2=Gbuf[i2], g3=Gbuf[i2+1];
                C[i0]   += a0/(1.f+__expf(-g0));
                C[i0+1] += a1/(1.f+__expf(-g1));
                C[i2]   += a2/(1.f+__expf(-g2));
                C[i2+1] += a3/(1.f+__expf(-g3));
            } else {
                float g0=Gbuf[i0], g1=Gbuf[i0+1], g2=Gbuf[i2], g3=Gbuf[i2+1];
                C[i0]   = tf32r(a0*g0/(1.f+__expf(-g0)));
                C[i0+1] = tf32r(a1*g1/(1.f+__expf(-g1)));
                C[i2]   = tf32r(a2*g2/(1.f+__expf(-g2)));
                C[i2+1] = tf32r(a3*g3/(1.f+__expf(-g3)));
            }
        }
    }
}

// ---------------- weight repack (tf32-rounded, K-major packed) --------------
__global__ void k_prep(
    const float* __restrict__ fgW,const float* __restrict__ fgA,const float* __restrict__ fgB,
    const float* __restrict__ guW,const float* __restrict__ guA,const float* __restrict__ guB,
    const float* __restrict__ ffgW,const float* __restrict__ ffgA,const float* __restrict__ ffgB,
    const float* __restrict__ fffW,const float* __restrict__ fffA,const float* __restrict__ fffB,
    const float* __restrict__ ffpW,const float* __restrict__ ffpA,const float* __restrict__ ffpB)
{
    const int S1=8*288*128, S2=S1, S3=8*160*384, S4=S3, S5=8*384*128;
    const int S6=1024*128, S7=1024*128, S8=3072*128;
    const int TOT=S1+S2+S3+S4+S5+S6+S7+S8;
    for(int idx=blockIdx.x*blockDim.x+threadIdx.x; idx<TOT; idx+=gridDim.x*blockDim.x){
        int i=idx; float v=0.f; float* dst;
        if(i<S1){ int b=i/36864,r=i%36864,k=r>>7,n=r&127,row=b*128+n;
            v = (k<256)? fgW[row*256+k] : fgA[row*32+(k-256)]; dst=&g_WBfg[i];
        } else if((i-=S1)<S2){ int b=i/36864,r=i%36864,k=r>>7,n=r&127,row=b*128+n;
            v = (k<256)? guW[row*256+k] : guA[row*32+(k-256)]; dst=&g_WBgu[i];
        } else if((i-=S2)<S3){ int b=i/61440,r=i%61440,k=r/384,n=r%384;
            if(n<352){ int row=b*352+n; v=(k<128)? ffgW[row*128+k] : ffgA[row*32+(k-128)]; }
            dst=&g_WBffg[i];
        } else if((i-=S3)<S4){ int b=i/61440,r=i%61440,k=r/384,n=r%384;
            if(n<352){ int row=b*352+n; v=(k<128)? fffW[row*128+k] : fffA[row*32+(k-128)]; }
            dst=&g_WBfff[i];
        } else if((i-=S4)<S5){ int b=i/49152,r=i%49152,k=r>>7,n=r&127,row=b*128+n;
            v = (k<352)? ffpW[row*352+k] : ffpA[row*32+(k-352)]; dst=&g_WBffp[i];
        } else if((i-=S5)<S6){ int k=i>>7,c=i&127;
            v = (c<32)? fgB[c*2048+k] : (c<64)? fgB[(c-32)*2048+1024+k]
              : (c<96)? guB[(c-64)*2048+k] : guB[(c-96)*2048+1024+k];
            dst=&g_PB[i];
        } else if((i-=S6)<S7){ int k=i>>7,c=i&127;
            v = (c<32)? ffgB[c*1024+k] : (c<64)? fffB[(c-32)*1024+k] : 0.f;
            dst=&g_PB2[i];
        } else { i-=S7; int k=i>>7,c=i&127,kk=k%384;
            v = (c<32 && kk<352)? ffpB[c*2816 + (k/384)*352 + kk] : 0.f;
            dst=&g_PB3[i];
        }
        *dst = tf32r(v);
    }
}

// ---------------- rmsnorm: one warp per token, write tf32-rounded Z ---------
__global__ void __launch_bounds__(256) k_rms(const float* __restrict__ H){
    int warp=threadIdx.x>>5, lane=threadIdx.x&31;
    int m=blockIdx.x*8+warp;
    const float4* hp=reinterpret_cast<const float4*>(H)+(size_t)m*256;
    float4 v[8]; float ss=0.f;
#pragma unroll
    for(int j=0;j<8;j++){ v[j]=hp[j*32+lane];
        ss+=v[j].x*v[j].x+v[j].y*v[j].y+v[j].z*v[j].z+v[j].w*v[j].w; }
#pragma unroll
    for(int o=16;o;o>>=1) ss+=__shfl_xor_sync(0xffffffffu,ss,o);
    float sc=rsqrtf(ss*(1.f/1024.f)+1.1920929e-07f);
    float4* zp=reinterpret_cast<float4*>(g_Z)+(size_t)m*256;
#pragma unroll
    for(int j=0;j<8;j++){ float4 o4;
        o4.x=tf32r(v[j].x*sc); o4.y=tf32r(v[j].y*sc);
        o4.z=tf32r(v[j].z*sc); o4.w=tf32r(v[j].w*sc);
        zp[j*32+lane]=o4; }
}

// R[m,c<32]=r_fg, R[m,32..63]=r_gu  (shift part from previous token's P)
__global__ void k_r1(){
    int idx=blockIdx.x*blockDim.x+threadIdx.x;
    if(idx>=MTOK*64) return;
    int m=idx>>6, c=idx&63;
    int base=(c<32)? c : c+32;
    float v=g_P[(size_t)m*128+base];
    if(m&2047) v+=g_P[(size_t)(m-1)*128+base+32];
    g_R[idx]=tf32r(v);
}

// ---------------------------------------------------------------------------
extern "C" void kernel_launch(void* const* d_in, const int* in_sizes, int n_in,
                              void* d_out, int out_size)
{
    (void)in_sizes; (void)n_in; (void)out_size;
    const float* x   =(const float*)d_in[0];
    const float* fgW =(const float*)d_in[1],  *fgA =(const float*)d_in[2],  *fgB =(const float*)d_in[3];
    const float* guW =(const float*)d_in[4],  *guA =(const float*)d_in[5],  *guB =(const float*)d_in[6];
    const float* ffgW=(const float*)d_in[7],  *ffgA=(const float*)d_in[8],  *ffgB=(const float*)d_in[9];
    const float* fffW=(const float*)d_in[10], *fffA=(const float*)d_in[11], *fffB=(const float*)d_in[12];
    const float* ffpW=(const float*)d_in[13], *ffpA=(const float*)d_in[14], *ffpB=(const float*)d_in[15];
    float* H=(float*)d_out;

    cudaFuncSetAttribute(k_gemm, cudaFuncAttributeMaxDynamicSharedMemorySize, SMEMB);

    float *Z,*P,*R,*P2,*P3,*G,*FG,*WBfg,*WBgu,*WBffg,*WBfff,*WBffp,*PB,*PB2,*PB3;
    cudaGetSymbolAddress((void**)&Z,  g_Z );  cudaGetSymbolAddress((void**)&P,  g_P );
    cudaGetSymbolAddress((void**)&R,  g_R );  cudaGetSymbolAddress((void**)&P2, g_P2);
    cudaGetSymbolAddress((void**)&P3, g_P3);  cudaGetSymbolAddress((void**)&G,  g_G );
    cudaGetSymbolAddress((void**)&FG, g_FG);  cudaGetSymbolAddress((void**)&WBfg, g_WBfg);
    cudaGetSymbolAddress((void**)&WBgu, g_WBgu); cudaGetSymbolAddress((void**)&WBffg,g_WBffg);
    cudaGetSymbolAddress((void**)&WBfff,g_WBfff);cudaGetSymbolAddress((void**)&WBffp,g_WBffp);
    cudaGetSymbolAddress((void**)&PB, g_PB);  cudaGetSymbolAddress((void**)&PB2,g_PB2);
    cudaGetSymbolAddress((void**)&PB3,g_PB3);

    cudaMemcpyAsync(H, x, (size_t)MTOK*1024*sizeof(float), cudaMemcpyDeviceToDevice);
    k_prep<<<4096,256>>>(fgW,fgA,fgB,guW,guA,guB,ffgW,ffgA,ffgB,fffW,fffA,fffB,ffpW,ffpA,ffpB);

    dim3 g1(128,1,1), gBlk(128,8,1), gFf(128,8,3);
    const float* NUL=0;
    for(int it=0; it<4; it++){
        k_rms<<<2048,256>>>(H);
        // P = Z @ [B1fg|B2fg|B1gu|B2gu]^T   (K=1024, N=128)
        k_gemm<<<g1,512,SMEMB>>>(Z,1024,0,0, NUL,0,0, PB,128,0, P,128,0,
                                 NUL,NUL, 1024,1024,0,0);
        k_r1<<<MTOK*64/256,256>>>();
        // gate GEMM (K=256+32) -> G
        k_gemm<<<gBlk,512,SMEMB>>>(Z,1024,256,1, R,64,0,  WBfg,128,288*128, G,1024,128,
                                   NUL,NUL, 256,288,0,0);
        // update GEMM fused: H += sigmoid(G)*acc
        k_gemm<<<gBlk,512,SMEMB>>>(Z,1024,256,1, R,64,32, WBgu,128,288*128, H,1024,128,
                                   NUL,G, 256,288,0,1);
    }
    k_rms<<<2048,256>>>(H);
    // P2 = Z @ [Bffg|Bfff]^T (N padded to 128)
    k_gemm<<<g1,512,SMEMB>>>(Z,1024,0,0, NUL,0,0, PB2,128,0, P2,128,0,
                             NUL,NUL, 1024,1024,1,0);
    // ffg (K=128+32, N padded 384/block) -> FG (raw gate values)
    k_gemm<<<gFf,512,SMEMB>>>(Z,1024,128,0, P2,128,0,  WBffg,384,160*384, FG,3072,384,
                              NUL,NUL, 128,160,0,0);
    // fff fused: FG = tf32r(silu(FG)*acc)
    k_gemm<<<gFf,512,SMEMB>>>(Z,1024,128,0, P2,128,32, WBfff,384,160*384, FG,3072,384,
                              NUL,FG, 128,160,0,2);
    // P3 = FF @ Bffp^T (padded K=3072, N=128)
    k_gemm<<<g1,512,SMEMB>>>(FG,3072,0,0, NUL,0,0, PB3,128,0, P3,128,0,
                             NUL,NUL, 3072,3072,1,0);
    // out = h + ffp(FF)   (K=352+32)
    k_gemm<<<gBlk,512,SMEMB>>>(FG,3072,384,0, P3,128,0, WBffp,128,384*128, H,1024,128,
                               H,NUL, 352,384,0,0);
}

// round 12
// speedup vs baseline: 1.2374x; 1.2097x over previous
#include <cuda_runtime.h>
#include <stdint.h>

#define DINL __device__ __forceinline__
constexpr int MTOK = 16384;   // 8 * 2048 tokens

// ---------------- scratch (device globals; no dynamic alloc) ----------------
__device__ __align__(16) float g_Z [MTOK*1024];
__device__ __align__(16) float g_P [MTOK*128];
__device__ __align__(16) float g_R [MTOK*64];
__device__ __align__(16) float g_P2[MTOK*128];
__device__ __align__(16) float g_P3[MTOK*128];
__device__ __align__(16) float g_G [MTOK*1024];
__device__ __align__(16) float g_FG[(size_t)MTOK*3072];
// packed tf32 weights, K-major [K][N]
__device__ __align__(16) float g_WBfg [8*288*128];
__device__ __align__(16) float g_WBgu [8*288*128];
__device__ __align__(16) float g_WBffg[8*160*384];
__device__ __align__(16) float g_WBfff[8*160*384];
__device__ __align__(16) float g_WBffp[8*384*128];
__device__ __align__(16) float g_PB  [1024*128];
__device__ __align__(16) float g_PB2 [1024*128];
__device__ __align__(16) float g_PB3 [3072*128];

DINL float tf32r(float x){ unsigned u; asm("cvt.rna.tf32.f32 %0,%1;":"=r"(u):"f"(x)); return __uint_as_float(u); }

DINL void mma8(float* d, const unsigned* a, const unsigned* b){
    asm volatile("mma.sync.aligned.m16n8k8.row.col.f32.tf32.tf32.f32 "
        "{%0,%1,%2,%3},{%4,%5,%6,%7},{%8,%9},{%0,%1,%2,%3};"
        :"+f"(d[0]),"+f"(d[1]),"+f"(d[2]),"+f"(d[3])
        :"r"(a[0]),"r"(a[1]),"r"(a[2]),"r"(a[3]),"r"(b[0]),"r"(b[1]));
}
DINL void cpa16(uint32_t s, const void* g, int sz){
    asm volatile("cp.async.cg.shared.global [%0], [%1], 16, %2;"::"r"(s),"l"(g),"r"(sz));
}
DINL void cpcommit(){ asm volatile("cp.async.commit_group;"); }
template<int N> DINL void cpwait(){ asm volatile("cp.async.wait_group %0;"::"n"(N)); }

// ---------------------------------------------------------------------------
// GEMM: C[128 x 128] per (mtile, diag-block b, n-tile). K-chunk 32,
// 4-stage cp.async pipeline, ONE __syncthreads per step.
// A region1 (k<K1): A1[(m-shift)*lda1+aoff+k] (zero row at seq start if shift).
// A region2: A2[m*lda2+a2off+k-K1].
// mode 0: C = (acc + Hadd?) (tf32r if roundC)
// mode 1: C += sigmoid(Gbuf)*acc            (gate-update fusion, C==H)
// mode 2: C  = tf32r(silu(Gbuf)*acc)        (ff fusion, Gbuf==C==FG)
// ---------------------------------------------------------------------------
constexpr int STAGES = 4;
constexpr int ASZ = 128*36;    // per-stage A floats
constexpr int BSZ = 32*136;    // per-stage B floats
constexpr int SMEMB = STAGES*(ASZ+BSZ)*4;   // 143360 bytes

__global__ void __launch_bounds__(512,1) k_gemm(
    const float* __restrict__ A1, int lda1, int blkStrideA, int shiftMode,
    const float* __restrict__ A2, int lda2, int a2off,
    const float* __restrict__ Bw, int ldbN, int bBlkStride,
    float* __restrict__ C, int ldc, int cBlkStride,
    const float* __restrict__ Hadd, const float* __restrict__ Gbuf,
    int K1, int KTOT, int roundC, int mode)
{
    extern __shared__ float sm[];
    const int b = blockIdx.y, nt = blockIdx.z;
    bool shift=false; int aoff;
    if (shiftMode){ shift=(b>=4); aoff=(b&3)*blkStrideA; } else aoff=b*blkStrideA;
    const float* Bp = Bw + (size_t)b*bBlkStride + nt*128;
    const int tid=threadIdx.x, warp=tid>>5, lane=tid&31;
    const int wm=warp>>2, wn=warp&3, gid=lane>>2, tig=lane&3;
    const int m0=blockIdx.x*128;
    const int nsteps = KTOT/32;

    float acc[2][4][4];
#pragma unroll
    for(int i=0;i<2;i++)
#pragma unroll
        for(int j=0;j<4;j++)
#pragma unroll
            for(int q=0;q<4;q++) acc[i][j][q]=0.f;

    auto fill=[&](int st, int k0){
        float* As = sm + st*ASZ;
        float* Bs = sm + STAGES*ASZ + st*BSZ;
        bool r1 = (k0 < K1);
#pragma unroll
        for(int j=0;j<2;j++){
            int id = tid + j*512;          // 0..1023  -> A 128x32
            int row = id>>3, kc=(id&7)*4;
            uint32_t sa = (uint32_t)__cvta_generic_to_shared(&As[row*36+kc]);
            int m=m0+row; int sz=16; const float* gp;
            if(r1){
                int mm=m;
                if(shift){ if((m&2047)==0) sz=0; else mm=m-1; }
                gp = &A1[(size_t)mm*lda1 + aoff + k0 + kc];
            } else {
                gp = &A2[(size_t)m*lda2 + a2off + (k0-K1) + kc];
            }
            cpa16(sa, gp, sz);
        }
#pragma unroll
        for(int j=0;j<2;j++){
            int id = tid + j*512;          // 0..1023  -> B 32x128
            int r=id>>5, c=(id&31)*4;
            uint32_t sb = (uint32_t)__cvta_generic_to_shared(&Bs[r*136+c]);
            cpa16(sb, &Bp[(size_t)(k0+r)*ldbN + c], 16);
        }
    };

    // prologue: stages 0..2
#pragma unroll
    for(int p=0;p<STAGES-1;p++){
        if(p<nsteps) fill(p, p*32);
        cpcommit();
    }

    for(int s=0;s<nsteps;s++){
        const int st = s & (STAGES-1);
        cpwait<STAGES-2>();          // stage s data complete
        __syncthreads();             // visible to all; all warps done with stage (s-1)
        {   // refill buffer (s+3)&3 == (s-1)&3, consumed at step s-1
            int nf_ = s + STAGES - 1;
            if(nf_ < nsteps) fill(nf_ & (STAGES-1), nf_*32);
            cpcommit();              // commit (possibly empty) keeps group count aligned
        }
        const float* AsS = sm + st*ASZ;
        const float* BsS = sm + STAGES*ASZ + st*BSZ;
#pragma unroll
        for(int k8=0;k8<4;k8++){
            unsigned af[2][4];
#pragma unroll
            for(int mf=0;mf<2;mf++){
                int r0=wm*32+mf*16+gid, c=k8*8+tig;
                af[mf][0]=__float_as_uint(AsS[r0*36+c]);
                af[mf][1]=__float_as_uint(AsS[(r0+8)*36+c]);
                af[mf][2]=__float_as_uint(AsS[r0*36+c+4]);
                af[mf][3]=__float_as_uint(AsS[(r0+8)*36+c+4]);
            }
#pragma unroll
            for(int nf=0;nf<4;nf++){
                unsigned bf[2];
                int col=wn*32+nf*8+gid;
                bf[0]=__float_as_uint(BsS[(k8*8+tig)*136+col]);
                bf[1]=__float_as_uint(BsS[(k8*8+tig+4)*136+col]);
                mma8(acc[0][nf],af[0],bf);
                mma8(acc[1][nf],af[1],bf);
            }
        }
    }

    const int coff = b*cBlkStride + nt*128;
#pragma unroll
    for(int mf=0;mf<2;mf++){
        int m=m0+wm*32+mf*16+gid;
#pragma unroll
        for(int nf=0;nf<4;nf++){
            int col=coff+wn*32+nf*8+2*tig;
            size_t i0=(size_t)m*ldc+col, i2=(size_t)(m+8)*ldc+col;
            float a0=acc[mf][nf][0], a1=acc[mf][nf][1], a2=acc[mf][nf][2], a3=acc[mf][nf][3];
            if(mode==0){
                if(Hadd){ a0+=Hadd[i0]; a1+=Hadd[i0+1]; a2+=Hadd[i2]; a3+=Hadd[i2+1]; }
                if(roundC){ a0=tf32r(a0); a1=tf32r(a1); a2=tf32r(a2); a3=tf32r(a3); }
                C[i0]=a0; C[i0+1]=a1; C[i2]=a2; C[i2+1]=a3;
            } else if(mode==1){
                float g0=Gbuf[i0], g1=Gbuf[i0+1], g2=Gbuf[i2], g3=Gbuf[i2+1];
                C[i0]   += a0/(1.f+__expf(-g0));
                C[i0+1] += a1/(1.f+__expf(-g1));
                C[i2]   += a2/(1.f+__expf(-g2));
                C[i2+1] += a3/(1.f+__expf(-g3));
            } else {
                float g0=Gbuf[i0], g1=Gbuf[i0+1], g2=Gbuf[i2], g3=Gbuf[i2+1];
                C[i0]   = tf32r(a0*g0/(1.f+__expf(-g0)));
                C[i0+1] = tf32r(a1*g1/(1.f+__expf(-g1)));
                C[i2]   = tf32r(a2*g2/(1.f+__expf(-g2)));
                C[i2+1] = tf32r(a3*g3/(1.f+__expf(-g3)));
            }
        }
    }
}

// ---------------- weight repack (tf32-rounded, K-major packed) --------------
__global__ void k_prep(
    const float* __restrict__ fgW,const float* __restrict__ fgA,const float* __restrict__ fgB,
    const float* __restrict__ guW,const float* __restrict__ guA,const float* __restrict__ guB,
    const float* __restrict__ ffgW,const float* __restrict__ ffgA,const float* __restrict__ ffgB,
    const float* __restrict__ fffW,const float* __restrict__ fffA,const float* __restrict__ fffB,
    const float* __restrict__ ffpW,const float* __restrict__ ffpA,const float* __restrict__ ffpB)
{
    const int S1=8*288*128, S2=S1, S3=8*160*384, S4=S3, S5=8*384*128;
    const int S6=1024*128, S7=1024*128, S8=3072*128;
    const int TOT=S1+S2+S3+S4+S5+S6+S7+S8;
    for(int idx=blockIdx.x*blockDim.x+threadIdx.x; idx<TOT; idx+=gridDim.x*blockDim.x){
        int i=idx; float v=0.f; float* dst;
        if(i<S1){ int b=i/36864,r=i%36864,k=r>>7,n=r&127,row=b*128+n;
            v = (k<256)? fgW[row*256+k] : fgA[row*32+(k-256)]; dst=&g_WBfg[i];
        } else if((i-=S1)<S2){ int b=i/36864,r=i%36864,k=r>>7,n=r&127,row=b*128+n;
            v = (k<256)? guW[row*256+k] : guA[row*32+(k-256)]; dst=&g_WBgu[i];
        } else if((i-=S2)<S3){ int b=i/61440,r=i%61440,k=r/384,n=r%384;
            if(n<352){ int row=b*352+n; v=(k<128)? ffgW[row*128+k] : ffgA[row*32+(k-128)]; }
            dst=&g_WBffg[i];
        } else if((i-=S3)<S4){ int b=i/61440,r=i%61440,k=r/384,n=r%384;
            if(n<352){ int row=b*352+n; v=(k<128)? fffW[row*128+k] : fffA[row*32+(k-128)]; }
            dst=&g_WBfff[i];
        } else if((i-=S4)<S5){ int b=i/49152,r=i%49152,k=r>>7,n=r&127,row=b*128+n;
            v = (k<352)? ffpW[row*352+k] : ffpA[row*32+(k-352)]; dst=&g_WBffp[i];
        } else if((i-=S5)<S6){ int k=i>>7,c=i&127;
            v = (c<32)? fgB[c*2048+k] : (c<64)? fgB[(c-32)*2048+1024+k]
              : (c<96)? guB[(c-64)*2048+k] : guB[(c-96)*2048+1024+k];
            dst=&g_PB[i];
        } else if((i-=S6)<S7){ int k=i>>7,c=i&127;
            v = (c<32)? ffgB[c*1024+k] : (c<64)? fffB[(c-32)*1024+k] : 0.f;
            dst=&g_PB2[i];
        } else { i-=S7; int k=i>>7,c=i&127,kk=k%384;
            v = (c<32 && kk<352)? ffpB[c*2816 + (k/384)*352 + kk] : 0.f;
            dst=&g_PB3[i];
        }
        *dst = tf32r(v);
    }
}

// ---------------- rmsnorm: one warp per token, write tf32-rounded Z ---------
__global__ void __launch_bounds__(256) k_rms(const float* __restrict__ H){
    int warp=threadIdx.x>>5, lane=threadIdx.x&31;
    int m=blockIdx.x*8+warp;
    const float4* hp=reinterpret_cast<const float4*>(H)+(size_t)m*256;
    float4 v[8]; float ss=0.f;
#pragma unroll
    for(int j=0;j<8;j++){ v[j]=hp[j*32+lane];
        ss+=v[j].x*v[j].x+v[j].y*v[j].y+v[j].z*v[j].z+v[j].w*v[j].w; }
#pragma unroll
    for(int o=16;o;o>>=1) ss+=__shfl_xor_sync(0xffffffffu,ss,o);
    float sc=rsqrtf(ss*(1.f/1024.f)+1.1920929e-07f);
    float4* zp=reinterpret_cast<float4*>(g_Z)+(size_t)m*256;
#pragma unroll
    for(int j=0;j<8;j++){ float4 o4;
        o4.x=tf32r(v[j].x*sc); o4.y=tf32r(v[j].y*sc);
        o4.z=tf32r(v[j].z*sc); o4.w=tf32r(v[j].w*sc);
        zp[j*32+lane]=o4; }
}

// R[m,c<32]=r_fg, R[m,32..63]=r_gu  (shift part from previous token's P)
__global__ void k_r1(){
    int idx=blockIdx.x*blockDim.x+threadIdx.x;
    if(idx>=MTOK*64) return;
    int m=idx>>6, c=idx&63;
    int base=(c<32)? c : c+32;
    float v=g_P[(size_t)m*128+base];
    if(m&2047) v+=g_P[(size_t)(m-1)*128+base+32];
    g_R[idx]=tf32r(v);
}

// ---------------------------------------------------------------------------
extern "C" void kernel_launch(void* const* d_in, const int* in_sizes, int n_in,
                              void* d_out, int out_size)
{
    (void)in_sizes; (void)n_in; (void)out_size;
    const float* x   =(const float*)d_in[0];
    const float* fgW =(const float*)d_in[1],  *fgA =(const float*)d_in[2],  *fgB =(const float*)d_in[3];
    const float* guW =(const float*)d_in[4],  *guA =(const float*)d_in[5],  *guB =(const float*)d_in[6];
    const float* ffgW=(const float*)d_in[7],  *ffgA=(const float*)d_in[8],  *ffgB=(const float*)d_in[9];
    const float* fffW=(const float*)d_in[10], *fffA=(const float*)d_in[11], *fffB=(const float*)d_in[12];
    const float* ffpW=(const float*)d_in[13], *ffpA=(const float*)d_in[14], *ffpB=(const float*)d_in[15];
    float* H=(float*)d_out;

    cudaFuncSetAttribute(k_gemm, cudaFuncAttributeMaxDynamicSharedMemorySize, SMEMB);

    float *Z,*P,*R,*P2,*P3,*G,*FG,*WBfg,*WBgu,*WBffg,*WBfff,*WBffp,*PB,*PB2,*PB3;
    cudaGetSymbolAddress((void**)&Z,  g_Z );  cudaGetSymbolAddress((void**)&P,  g_P );
    cudaGetSymbolAddress((void**)&R,  g_R );  cudaGetSymbolAddress((void**)&P2, g_P2);
    cudaGetSymbolAddress((void**)&P3, g_P3);  cudaGetSymbolAddress((void**)&G,  g_G );
    cudaGetSymbolAddress((void**)&FG, g_FG);  cudaGetSymbolAddress((void**)&WBfg, g_WBfg);
    cudaGetSymbolAddress((void**)&WBgu, g_WBgu); cudaGetSymbolAddress((void**)&WBffg,g_WBffg);
    cudaGetSymbolAddress((void**)&WBfff,g_WBfff);cudaGetSymbolAddress((void**)&WBffp,g_WBffp);
    cudaGetSymbolAddress((void**)&PB, g_PB);  cudaGetSymbolAddress((void**)&PB2,g_PB2);
    cudaGetSymbolAddress((void**)&PB3,g_PB3);

    cudaMemcpyAsync(H, x, (size_t)MTOK*1024*sizeof(float), cudaMemcpyDeviceToDevice);
    k_prep<<<4096,256>>>(fgW,fgA,fgB,guW,guA,guB,ffgW,ffgA,ffgB,fffW,fffA,fffB,ffpW,ffpA,ffpB);

    dim3 g1(128,1,1), gBlk(128,8,1), gFf(128,8,3);
    const float* NUL=0;
    for(int it=0; it<4; it++){
        k_rms<<<2048,256>>>(H);
        // P = Z @ [B1fg|B2fg|B1gu|B2gu]^T   (K=1024, N=128)
        k_gemm<<<g1,512,SMEMB>>>(Z,1024,0,0, NUL,0,0, PB,128,0, P,128,0,
                                 NUL,NUL, 1024,1024,0,0);
        k_r1<<<MTOK*64/256,256>>>();
        // gate GEMM (K=256+32) -> G
        k_gemm<<<gBlk,512,SMEMB>>>(Z,1024,256,1, R,64,0,  WBfg,128,288*128, G,1024,128,
                                   NUL,NUL, 256,288,0,0);
        // update GEMM fused: H += sigmoid(G)*acc
        k_gemm<<<gBlk,512,SMEMB>>>(Z,1024,256,1, R,64,32, WBgu,128,288*128, H,1024,128,
                                   NUL,G, 256,288,0,1);
    }
    k_rms<<<2048,256>>>(H);
    // P2 = Z @ [Bffg|Bfff]^T (N padded to 128)
    k_gemm<<<g1,512,SMEMB>>>(Z,1024,0,0, NUL,0,0, PB2,128,0, P2,128,0,
                             NUL,NUL, 1024,1024,1,0);
    // ffg (K=128+32, N padded 384/block) -> FG (raw gate values)
    k_gemm<<<gFf,512,SMEMB>>>(Z,1024,128,0, P2,128,0,  WBffg,384,160*384, FG,3072,384,
                              NUL,NUL, 128,160,0,0);
    // fff fused: FG = tf32r(silu(FG)*acc)
    k_gemm<<<gFf,512,SMEMB>>>(Z,1024,128,0, P2,128,32, WBfff,384,160*384, FG,3072,384,
                              NUL,FG, 128,160,0,2);
    // P3 = FF @ Bffp^T (padded K=3072, N=128)
    k_gemm<<<g1,512,SMEMB>>>(FG,3072,0,0, NUL,0,0, PB3,128,0, P3,128,0,
                             NUL,NUL, 3072,3072,1,0);
    // out = h + ffp(FF)   (K=352+32)
    k_gemm<<<gBlk,512,SMEMB>>>(FG,3072,384,0, P3,128,0, WBffp,128,384*128, H,1024,128,
                               H,NUL, 352,384,0,0);
}

// round 16
// speedup vs baseline: 1.4310x; 1.1564x over previous
#include <cuda_runtime.h>
#include <stdint.h>

#define DINL __device__ __forceinline__
constexpr int MTOK = 16384;   // 8 * 2048 tokens

// ---------------- scratch (device globals; no dynamic alloc) ----------------
__device__ __align__(16) float g_Z [MTOK*1024];
__device__ __align__(16) float g_P [MTOK*128];
__device__ __align__(16) float g_R [MTOK*64];
__device__ __align__(16) float g_P2[MTOK*128];
__device__ __align__(16) float g_P3[MTOK*128];
__device__ __align__(16) float g_G [MTOK*1024];
__device__ __align__(16) float g_FG[(size_t)MTOK*3072];
// packed tf32 weights, K-major [K][N]
__device__ __align__(16) float g_WBfg [8*288*128];
__device__ __align__(16) float g_WBgu [8*288*128];
__device__ __align__(16) float g_WBffg[8*160*384];
__device__ __align__(16) float g_WBfff[8*160*384];
__device__ __align__(16) float g_WBffp[8*384*128];
__device__ __align__(16) float g_PB  [1024*128];
__device__ __align__(16) float g_PB2 [1024*128];
__device__ __align__(16) float g_PB3 [3072*128];

DINL float tf32r(float x){ unsigned u; asm("cvt.rna.tf32.f32 %0,%1;":"=r"(u):"f"(x)); return __uint_as_float(u); }

DINL void mma8(float* d, const unsigned* a, const unsigned* b){
    asm volatile("mma.sync.aligned.m16n8k8.row.col.f32.tf32.tf32.f32 "
        "{%0,%1,%2,%3},{%4,%5,%6,%7},{%8,%9},{%0,%1,%2,%3};"
        :"+f"(d[0]),"+f"(d[1]),"+f"(d[2]),"+f"(d[3])
        :"r"(a[0]),"r"(a[1]),"r"(a[2]),"r"(a[3]),"r"(b[0]),"r"(b[1]));
}
DINL void cpa16(uint32_t s, const void* g, int sz){
    asm volatile("cp.async.cg.shared.global [%0], [%1], 16, %2;"::"r"(s),"l"(g),"r"(sz));
}
DINL void cpcommit(){ asm volatile("cp.async.commit_group;"); }
template<int N> DINL void cpwait(){ asm volatile("cp.async.wait_group %0;"::"n"(N)); }

// ---------------------------------------------------------------------------
// GEMM: C[128 x 128] per (mtile, diag-block b, n-tile). K-chunk 32,
// 3-stage cp.async pipeline, ONE __syncthreads per step, 2 CTAs/SM.
// A region1 (k<K1): A1[(m-shift)*lda1+aoff+k] (zero row at seq start if shift).
// A region2: A2[m*lda2+a2off+k-K1].
// mode 0: C = (acc + Hadd?) (tf32r if roundC)
// mode 1: C += sigmoid(Gbuf)*acc            (gate-update fusion, C==H)
// mode 2: C  = tf32r(silu(Gbuf)*acc)        (ff fusion, Gbuf==C==FG)
// ---------------------------------------------------------------------------
constexpr int STAGES = 3;
constexpr int ASZ = 128*36;    // per-stage A floats (18432 B)
constexpr int BSZ = 32*136;    // per-stage B floats (17408 B)
constexpr int SMEMB = STAGES*(ASZ+BSZ)*4;   // 107520 bytes -> 2 CTAs/SM

__global__ void __launch_bounds__(512,2) k_gemm(
    const float* __restrict__ A1, int lda1, int blkStrideA, int shiftMode,
    const float* __restrict__ A2, int lda2, int a2off,
    const float* __restrict__ Bw, int ldbN, int bBlkStride,
    float* __restrict__ C, int ldc, int cBlkStride,
    const float* __restrict__ Hadd, const float* __restrict__ Gbuf,
    int K1, int KTOT, int roundC, int mode)
{
    extern __shared__ float sm[];
    const int b = blockIdx.y, nt = blockIdx.z;
    bool shift=false; int aoff;
    if (shiftMode){ shift=(b>=4); aoff=(b&3)*blkStrideA; } else aoff=b*blkStrideA;
    const float* Bp = Bw + (size_t)b*bBlkStride + nt*128;
    const int tid=threadIdx.x, warp=tid>>5, lane=tid&31;
    const int wm=warp>>2, wn=warp&3, gid=lane>>2, tig=lane&3;
    const int m0=blockIdx.x*128;
    const int nsteps = KTOT/32;

    float acc[2][4][4];
#pragma unroll
    for(int i=0;i<2;i++)
#pragma unroll
        for(int j=0;j<4;j++)
#pragma unroll
            for(int q=0;q<4;q++) acc[i][j][q]=0.f;

    auto fill=[&](int st, int k0){
        float* As = sm + st*ASZ;
        float* Bs = sm + STAGES*ASZ + st*BSZ;
        bool r1 = (k0 < K1);
#pragma unroll
        for(int j=0;j<2;j++){
            int id = tid + j*512;          // 0..1023  -> A 128x32
            int row = id>>3, kc=(id&7)*4;
            uint32_t sa = (uint32_t)__cvta_generic_to_shared(&As[row*36+kc]);
            int m=m0+row; int sz=16; const float* gp;
            if(r1){
                int mm=m;
                if(shift){ if((m&2047)==0) sz=0; else mm=m-1; }
                gp = &A1[(size_t)mm*lda1 + aoff + k0 + kc];
            } else {
                gp = &A2[(size_t)m*lda2 + a2off + (k0-K1) + kc];
            }
            cpa16(sa, gp, sz);
        }
#pragma unroll
        for(int j=0;j<2;j++){
            int id = tid + j*512;          // 0..1023  -> B 32x128
            int r=id>>5, c=(id&31)*4;
            uint32_t sb = (uint32_t)__cvta_generic_to_shared(&Bs[r*136+c]);
            cpa16(sb, &Bp[(size_t)(k0+r)*ldbN + c], 16);
        }
    };

    // prologue: fill stages 0..STAGES-2
#pragma unroll
    for(int p=0;p<STAGES-1;p++){
        if(p<nsteps) fill(p, p*32);
        cpcommit();
    }

    int st = 0;                 // stage holding chunk s
    int ft = STAGES-1;          // stage to fill next (chunk s+STAGES-1)
    for(int s=0;s<nsteps;s++){
        cpwait<STAGES-2>();          // chunk s resident in stage st
        __syncthreads();             // all warps done with compute(s-1) -> ft reusable
        {
            int nf_ = s + STAGES - 1;
            if(nf_ < nsteps) fill(ft, nf_*32);
            cpcommit();              // commit (possibly empty) keeps group count aligned
        }
        const float* AsS = sm + st*ASZ;
        const float* BsS = sm + STAGES*ASZ + st*BSZ;
#pragma unroll
        for(int k8=0;k8<4;k8++){
            unsigned af[2][4];
#pragma unroll
            for(int mf=0;mf<2;mf++){
                int r0=wm*32+mf*16+gid, c=k8*8+tig;
                af[mf][0]=__float_as_uint(AsS[r0*36+c]);
                af[mf][1]=__float_as_uint(AsS[(r0+8)*36+c]);
                af[mf][2]=__float_as_uint(AsS[r0*36+c+4]);
                af[mf][3]=__float_as_uint(AsS[(r0+8)*36+c+4]);
            }
#pragma unroll
            for(int nf=0;nf<4;nf++){
                unsigned bf[2];
                int col=wn*32+nf*8+gid;
                bf[0]=__float_as_uint(BsS[(k8*8+tig)*136+col]);
                bf[1]=__float_as_uint(BsS[(k8*8+tig+4)*136+col]);
                mma8(acc[0][nf],af[0],bf);
                mma8(acc[1][nf],af[1],bf);
            }
        }
        st = (st+1==STAGES)? 0 : st+1;
        ft = (ft+1==STAGES)? 0 : ft+1;
    }

    const int coff = b*cBlkStride + nt*128;
#pragma unroll
    for(int mf=0;mf<2;mf++){
        int m=m0+wm*32+mf*16+gid;
#pragma unroll
        for(int nf=0;nf<4;nf++){
            int col=coff+wn*32+nf*8+2*tig;
            size_t i0=(size_t)m*ldc+col, i2=(size_t)(m+8)*ldc+col;
            float a0=acc[mf][nf][0], a1=acc[mf][nf][1], a2=acc[mf][nf][2], a3=acc[mf][nf][3];
            if(mode==0){
                if(Hadd){ a0+=Hadd[i0]; a1+=Hadd[i0+1]; a2+=Hadd[i2]; a3+=Hadd[i2+1]; }
                if(roundC){ a0=tf32r(a0); a1=tf32r(a1); a2=tf32r(a2); a3=tf32r(a3); }
                C[i0]=a0; C[i0+1]=a1; C[i2]=a2; C[i2+1]=a3;
            } else if(mode==1){
                float g0=Gbuf[i0], g1=Gbuf[i0+1], g2=Gbuf[i2], g3=Gbuf[i2+1];
                C[i0]   += a0/(1.f+__expf(-g0));
                C[i0+1] += a1/(1.f+__expf(-g1));
                C[i2]   += a2/(1.f+__expf(-g2));
                C[i2+1] += a3/(1.f+__expf(-g3));
            } else {
                float g0=Gbuf[i0], g1=Gbuf[i0+1], g2=Gbuf[i2], g3=Gbuf[i2+1];
                C[i0]   = tf32r(a0*g0/(1.f+__expf(-g0)));
                C[i0+1] = tf32r(a1*g1/(1.f+__expf(-g1)));
                C[i2]   = tf32r(a2*g2/(1.f+__expf(-g2)));
                C[i2+1] = tf32r(a3*g3/(1.f+__expf(-g3)));
            }
        }
    }
}

// ---------------- weight repack (tf32-rounded, K-major packed) --------------
__global__ void k_prep(
    const float* __restrict__ fgW,const float* __restrict__ fgA,const float* __restrict__ fgB,
    const float* __restrict__ guW,const float* __restrict__ guA,const float* __restrict__ guB,
    const float* __restrict__ ffgW,const float* __restrict__ ffgA,const float* __restrict__ ffgB,
    const float* __restrict__ fffW,const float* __restrict__ fffA,const float* __restrict__ fffB,
    const float* __restrict__ ffpW,const float* __restrict__ ffpA,const float* __restrict__ ffpB)
{
    const int S1=8*288*128, S2=S1, S3=8*160*384, S4=S3, S5=8*384*128;
    const int S6=1024*128, S7=1024*128, S8=3072*128;
    const int TOT=S1+S2+S3+S4+S5+S6+S7+S8;
    for(int idx=blockIdx.x*blockDim.x+threadIdx.x; idx<TOT; idx+=gridDim.x*blockDim.x){
        int i=idx; float v=0.f; float* dst;
        if(i<S1){ int b=i/36864,r=i%36864,k=r>>7,n=r&127,row=b*128+n;
            v = (k<256)? fgW[row*256+k] : fgA[row*32+(k-256)]; dst=&g_WBfg[i];
        } else if((i-=S1)<S2){ int b=i/36864,r=i%36864,k=r>>7,n=r&127,row=b*128+n;
            v = (k<256)? guW[row*256+k] : guA[row*32+(k-256)]; dst=&g_WBgu[i];
        } else if((i-=S2)<S3){ int b=i/61440,r=i%61440,k=r/384,n=r%384;
            if(n<352){ int row=b*352+n; v=(k<128)? ffgW[row*128+k] : ffgA[row*32+(k-128)]; }
            dst=&g_WBffg[i];
        } else if((i-=S3)<S4){ int b=i/61440,r=i%61440,k=r/384,n=r%384;
            if(n<352){ int row=b*352+n; v=(k<128)? fffW[row*128+k] : fffA[row*32+(k-128)]; }
            dst=&g_WBfff[i];
        } else if((i-=S4)<S5){ int b=i/49152,r=i%49152,k=r>>7,n=r&127,row=b*128+n;
            v = (k<352)? ffpW[row*352+k] : ffpA[row*32+(k-352)]; dst=&g_WBffp[i];
        } else if((i-=S5)<S6){ int k=i>>7,c=i&127;
            v = (c<32)? fgB[c*2048+k] : (c<64)? fgB[(c-32)*2048+1024+k]
              : (c<96)? guB[(c-64)*2048+k] : guB[(c-96)*2048+1024+k];
            dst=&g_PB[i];
        } else if((i-=S6)<S7){ int k=i>>7,c=i&127;
            v = (c<32)? ffgB[c*1024+k] : (c<64)? fffB[(c-32)*1024+k] : 0.f;
            dst=&g_PB2[i];
        } else { i-=S7; int k=i>>7,c=i&127,kk=k%384;
            v = (c<32 && kk<352)? ffpB[c*2816 + (k/384)*352 + kk] : 0.f;
            dst=&g_PB3[i];
        }
        *dst = tf32r(v);
    }
}

// ---------------- rmsnorm: one warp per token, write tf32-rounded Z ---------
__global__ void __launch_bounds__(256) k_rms(const float* __restrict__ H){
    int warp=threadIdx.x>>5, lane=threadIdx.x&31;
    int m=blockIdx.x*8+warp;
    const float4* hp=reinterpret_cast<const float4*>(H)+(size_t)m*256;
    float4 v[8]; float ss=0.f;
#pragma unroll
    for(int j=0;j<8;j++){ v[j]=hp[j*32+lane];
        ss+=v[j].x*v[j].x+v[j].y*v[j].y+v[j].z*v[j].z+v[j].w*v[j].w; }
#pragma unroll
    for(int o=16;o;o>>=1) ss+=__shfl_xor_sync(0xffffffffu,ss,o);
    float sc=rsqrtf(ss*(1.f/1024.f)+1.1920929e-07f);
    float4* zp=reinterpret_cast<float4*>(g_Z)+(size_t)m*256;
#pragma unroll
    for(int j=0;j<8;j++){ float4 o4;
        o4.x=tf32r(v[j].x*sc); o4.y=tf32r(v[j].y*sc);
        o4.z=tf32r(v[j].z*sc); o4.w=tf32r(v[j].w*sc);
        zp[j*32+lane]=o4; }
}

// R[m,c<32]=r_fg, R[m,32..63]=r_gu  (shift part from previous token's P)
__global__ void k_r1(){
    int idx=blockIdx.x*blockDim.x+threadIdx.x;
    if(idx>=MTOK*64) return;
    int m=idx>>6, c=idx&63;
    int base=(c<32)? c : c+32;
    float v=g_P[(size_t)m*128+base];
    if(m&2047) v+=g_P[(size_t)(m-1)*128+base+32];
    g_R[idx]=tf32r(v);
}

// ---------------------------------------------------------------------------
extern "C" void kernel_launch(void* const* d_in, const int* in_sizes, int n_in,
                              void* d_out, int out_size)
{
    (void)in_sizes; (void)n_in; (void)out_size;
    const float* x   =(const float*)d_in[0];
    const float* fgW =(const float*)d_in[1],  *fgA =(const float*)d_in[2],  *fgB =(const float*)d_in[3];
    const float* guW =(const float*)d_in[4],  *guA =(const float*)d_in[5],  *guB =(const float*)d_in[6];
    const float* ffgW=(const float*)d_in[7],  *ffgA=(const float*)d_in[8],  *ffgB=(const float*)d_in[9];
    const float* fffW=(const float*)d_in[10], *fffA=(const float*)d_in[11], *fffB=(const float*)d_in[12];
    const float* ffpW=(const float*)d_in[13], *ffpA=(const float*)d_in[14], *ffpB=(const float*)d_in[15];
    float* H=(float*)d_out;

    cudaFuncSetAttribute(k_gemm, cudaFuncAttributeMaxDynamicSharedMemorySize, SMEMB);

    float *Z,*P,*R,*P2,*P3,*G,*FG,*WBfg,*WBgu,*WBffg,*WBfff,*WBffp,*PB,*PB2,*PB3;
    cudaGetSymbolAddress((void**)&Z,  g_Z );  cudaGetSymbolAddress((void**)&P,  g_P );
    cudaGetSymbolAddress((void**)&R,  g_R );  cudaGetSymbolAddress((void**)&P2, g_P2);
    cudaGetSymbolAddress((void**)&P3, g_P3);  cudaGetSymbolAddress((void**)&G,  g_G );
    cudaGetSymbolAddress((void**)&FG, g_FG);  cudaGetSymbolAddress((void**)&WBfg, g_WBfg);
    cudaGetSymbolAddress((void**)&WBgu, g_WBgu); cudaGetSymbolAddress((void**)&WBffg,g_WBffg);
    cudaGetSymbolAddress((void**)&WBfff,g_WBfff);cudaGetSymbolAddress((void**)&WBffp,g_WBffp);
    cudaGetSymbolAddress((void**)&PB, g_PB);  cudaGetSymbolAddress((void**)&PB2,g_PB2);
    cudaGetSymbolAddress((void**)&PB3,g_PB3);

    cudaMemcpyAsync(H, x, (size_t)MTOK*1024*sizeof(float), cudaMemcpyDeviceToDevice);
    k_prep<<<4096,256>>>(fgW,fgA,fgB,guW,guA,guB,ffgW,ffgA,ffgB,fffW,fffA,fffB,ffpW,ffpA,ffpB);

    dim3 g1(128,1,1), gBlk(128,8,1), gFf(128,8,3);
    const float* NUL=0;
    for(int it=0; it<4; it++){
        k_rms<<<2048,256>>>(H);
        // P = Z @ [B1fg|B2fg|B1gu|B2gu]^T   (K=1024, N=128)
        k_gemm<<<g1,512,SMEMB>>>(Z,1024,0,0, NUL,0,0, PB,128,0, P,128,0,
                                 NUL,NUL, 1024,1024,0,0);
        k_r1<<<MTOK*64/256,256>>>();
        // gate GEMM (K=256+32) -> G
        k_gemm<<<gBlk,512,SMEMB>>>(Z,1024,256,1, R,64,0,  WBfg,128,288*128, G,1024,128,
                                   NUL,NUL, 256,288,0,0);
        // update GEMM fused: H += sigmoid(G)*acc
        k_gemm<<<gBlk,512,SMEMB>>>(Z,1024,256,1, R,64,32, WBgu,128,288*128, H,1024,128,
                                   NUL,G, 256,288,0,1);
    }
    k_rms<<<2048,256>>>(H);
    // P2 = Z @ [Bffg|Bfff]^T (N padded to 128)
    k_gemm<<<g1,512,SMEMB>>>(Z,1024,0,0, NUL,0,0, PB2,128,0, P2,128,0,
                             NUL,NUL, 1024,1024,1,0);
    // ffg (K=128+32, N padded 384/block) -> FG (raw gate values)
    k_gemm<<<gFf,512,SMEMB>>>(Z,1024,128,0, P2,128,0,  WBffg,384,160*384, FG,3072,384,
                              NUL,NUL, 128,160,0,0);
    // fff fused: FG = tf32r(silu(FG)*acc)
    k_gemm<<<gFf,512,SMEMB>>>(Z,1024,128,0, P2,128,32, WBfff,384,160*384, FG,3072,384,
                              NUL,FG, 128,160,0,2);
    // P3 = FF @ Bffp^T (padded K=3072, N=128)
    k_gemm<<<g1,512,SMEMB>>>(FG,3072,0,0, NUL,0,0, PB3,128,0, P3,128,0,
                             NUL,NUL, 3072,3072,1,0);
    // out = h + ffp(FF)   (K=352+32)
    k_gemm<<<gBlk,512,SMEMB>>>(FG,3072,384,0, P3,128,0, WBffp,128,384*128, H,1024,128,
                               H,NUL, 352,384,0,0);
}